// round 10
// baseline (speedup 1.0000x reference)
#include <cuda_runtime.h>
#include <stdint.h>

// Problem constants (shapes fixed by dataset; index/full read from device).
#define M_ROWS   100000
#define D_FEAT   1024
#define BATCH_N  4096
#define D_VEC    (D_FEAT / 4)                 // 256 float4 per row
#define TOT_VEC  ((long)M_ROWS * (long)D_VEC) // 25,600,000 float4 per array

// Output layout (floats):
//   [0, M*D)            new_feat
//   [M*D, 2*M*D)        new_pred
//   [2*M*D, 2*M*D + M)  new_conf
//   +M                  conf_mean
//   +M+1                utilization
#define OUT_CONF_OFF  (2L * M_ROWS * D_FEAT)

// ---------------------------------------------------------------------------
// Single fused kernel (no cache hints — plain loads/stores; R5 showed
// __ldcs/__stcs cost ~3% of HBM bandwidth on this stream).
//   blocks [0, M_ROWS): block b = memory row b.
//     - 256 threads copy the 256 float4 slots of feat and pred for that row,
//       source selected by the circular-buffer predicate.
//     - thread 0 additionally writes new_conf[b] (same predicate, free).
//   block M_ROWS: computes conf_mean (4096-elem reduction) + utilization.
// ---------------------------------------------------------------------------
__global__ void __launch_bounds__(256)
pm_fused(const float4* __restrict__ feat,
         const float4* __restrict__ pred,
         const float*  __restrict__ conf,
         const float4* __restrict__ mfeat,
         const float4* __restrict__ mpred,
         const float*  __restrict__ mconf,
         const int*    __restrict__ midx,
         const int*    __restrict__ mfull,
         float4*       __restrict__ out)        // base of output buffer
{
    int b = blockIdx.x;
    int t = threadIdx.x;

    if (b < M_ROWS) {
        // ---- bulk circular-buffer copy ----
        int mi = *midx;
        int r  = b - mi;
        if (r < 0) r += M_ROWS;

        long j = ((long)b << 8) + t;            // row-major float4 index
        float4* out_feat = out;
        float4* out_pred = out + TOT_VEC;
        float*  out_conf = (float*)out + OUT_CONF_OFF;

        if (r < BATCH_N) {
            long src = ((long)r << 8) + t;
            out_feat[j] = feat[src];
            out_pred[j] = pred[src];
            if (t == 0) out_conf[b] = conf[r];
        } else {
            out_feat[j] = mfeat[j];
            out_pred[j] = mpred[j];
            if (t == 0) out_conf[b] = mconf[b];
        }
        return;
    }

    // ---- scalar block: conf_mean + utilization ----
    __shared__ float red[8];

    float s = 0.0f;
    #pragma unroll
    for (int i = 0; i < BATCH_N; i += 256)      // 16 values per thread
        s += conf[i + t];

    #pragma unroll
    for (int o = 16; o > 0; o >>= 1)
        s += __shfl_xor_sync(0xFFFFFFFFu, s, o);

    if ((t & 31) == 0) red[t >> 5] = s;
    __syncthreads();

    if (t < 32) {
        float v = (t < 8) ? red[t] : 0.0f;
        #pragma unroll
        for (int o = 4; o > 0; o >>= 1)
            v += __shfl_xor_sync(0xFFFFFFFFu, v, o);
        if (t == 0) {
            float* out_f = (float*)out;
            out_f[OUT_CONF_OFF + M_ROWS] = v / (float)BATCH_N;

            int  mi        = *midx;
            int  new_index = (mi + BATCH_N) % M_ROWS;
            bool wrapped   = (mi + BATCH_N) >= M_ROWS;
            bool full      = (*mfull != 0) || wrapped;
            out_f[OUT_CONF_OFF + M_ROWS + 1] =
                full ? 1.0f : (float)new_index / (float)M_ROWS;
        }
    }
}

// ---------------------------------------------------------------------------
extern "C" void kernel_launch(void* const* d_in, const int* in_sizes, int n_in,
                              void* d_out, int out_size)
{
    const float* features     = (const float*)d_in[0];
    const float* predictions  = (const float*)d_in[1];
    const float* confidences  = (const float*)d_in[2];
    const float* mem_feat     = (const float*)d_in[3];
    const float* mem_pred     = (const float*)d_in[4];
    const float* mem_conf     = (const float*)d_in[5];
    const int*   mem_index    = (const int*)d_in[6];
    const int*   mem_full     = (const int*)d_in[7];

    pm_fused<<<M_ROWS + 1, 256>>>(
        (const float4*)features, (const float4*)predictions, confidences,
        (const float4*)mem_feat, (const float4*)mem_pred, mem_conf,
        mem_index, mem_full, (float4*)d_out);
}